// round 16
// baseline (speedup 1.0000x reference)
#include <cuda_runtime.h>
#include <cuda_fp16.h>
#include <cstdint>
#include <math.h>

// ---------------------------------------------------------------------------
// Problem constants
// ---------------------------------------------------------------------------
#define BB 4
#define SS 1024
#define DD 1024
#define HH 16
#define HDIM 64
#define FF 2048
#define HID 4096
#define TOK (BB*SS)          // 4096 tokens
#define QKVN 3072
#define WSCALE (1.0f/64.0f)  // weights pre-scaled by 64 (fp16 subnormal guard)

// ---------------------------------------------------------------------------
// Scratch (__device__ globals; no allocation allowed)
// ---------------------------------------------------------------------------
__device__ float g_o   [TOK*DD];
__device__ float g_h   [TOK*DD];
__device__ float g_feat[TOK*DD];
__device__ float g_feat2[TOK*DD];
__device__ float g_s   [TOK];
__device__ float g_sv  [TOK];
__device__ int   g_seg [TOK];
__device__ float g_maxseg[BB];
__device__ float g_bqkv[QKVN];

// const rows for zero-pooled-row fast path
__device__ float  g_c1f[HID];
__device__ __half g_c1h[HID], g_c1l[HID];
__device__ float  g_c2f[HID];

// fp16 split activations
__device__ __half g_qkvh[TOK*QKVN], g_qkvl[TOK*QKVN];
__device__ __half g_xh[TOK*DD],    g_xl[TOK*DD];
__device__ __half g_fh[TOK*DD],    g_fl[TOK*DD];
__device__ __half g_ath[TOK*DD],   g_atl[TOK*DD];
__device__ __half g_hh[TOK*DD],    g_hl[TOK*DD];
__device__ __half g_ffh[TOK*FF],   g_ffl[TOK*FF];
__device__ __half g_plh[TOK*DD],   g_pll[TOK*DD];
__device__ __half g_phh[TOK*HID],  g_phl[TOK*HID];

// fp16 split weights [N,K] K-contiguous, pre-scaled x64
__device__ __half g_wqkvh[QKVN*DD], g_wqkvl[QKVN*DD];
__device__ __half g_woh[DD*DD],     g_wol[DD*DD];
__device__ __half g_w1h[FF*DD],     g_w1l[FF*DD];
__device__ __half g_w2h[DD*FF],     g_w2l[DD*FF];
__device__ __half g_p1h[HID*DD],    g_p1l[HID*DD];
__device__ __half g_p2h[HID*HID],   g_p2l[HID*HID];

// ---------------------------------------------------------------------------
// Helpers
// ---------------------------------------------------------------------------
__device__ __forceinline__ float gelu_f(float x) {
    return 0.5f * x * (1.0f + erff(x * 0.70710678118654752440f));
}

__device__ __forceinline__ void cp16(uint32_t dst, const void* src) {
    asm volatile("cp.async.cg.shared.global [%0], [%1], 16;\n"
                 :: "r"(dst), "l"(src));
}

__device__ __forceinline__ uint32_t smem_u32(const void* p) {
    uint32_t a;
    asm("{ .reg .u64 t; cvta.to.shared.u64 t, %1; cvt.u32.u64 %0, t; }"
        : "=r"(a) : "l"(p));
    return a;
}

// mma.sync m16n8k16 f16 with f32 accumulate
__device__ __forceinline__ void mma_f16(float* c,
                                        uint32_t a0, uint32_t a1,
                                        uint32_t a2, uint32_t a3,
                                        uint32_t b0, uint32_t b1) {
    asm volatile(
        "mma.sync.aligned.m16n8k16.row.col.f32.f16.f16.f32 "
        "{%0,%1,%2,%3}, {%4,%5,%6,%7}, {%8,%9}, {%0,%1,%2,%3};\n"
        : "+f"(c[0]), "+f"(c[1]), "+f"(c[2]), "+f"(c[3])
        : "r"(a0), "r"(a1), "r"(a2), "r"(a3), "r"(b0), "r"(b1));
}

__device__ __forceinline__ void ldsm_x4(uint32_t* r, uint32_t addr) {
    asm volatile(
        "ldmatrix.sync.aligned.m8n8.x4.shared.b16 {%0,%1,%2,%3}, [%4];\n"
        : "=r"(r[0]), "=r"(r[1]), "=r"(r[2]), "=r"(r[3]) : "r"(addr));
}

__device__ __forceinline__ void ldsm_x4_t(uint32_t* r, uint32_t addr) {
    asm volatile(
        "ldmatrix.sync.aligned.m8n8.x4.trans.shared.b16 {%0,%1,%2,%3}, [%4];\n"
        : "=r"(r[0]), "=r"(r[1]), "=r"(r[2]), "=r"(r[3]) : "r"(addr));
}

__device__ __forceinline__ void hsplit(float v, __half& h, __half& l) {
    h = __float2half(v);
    l = __float2half(v - __half2float(h));
}

// ---------------------------------------------------------------------------
// fp16 2-split GEMM, COMBOS = 3 (hh+hl+lh, fp32-grade) or 2 (hh+hl, ~2e-4).
// COMBOS==2: Al operand dropped entirely -> 3-array compact smem (60KB total)
// -> 3 CTAs/SM. COMBOS==3: 4-array smem (80KB), 2 CTAs/SM.
// maxseg path: all-zero pooled row tile -> write const row, or return with no
// write when crf/crh are null (rows provably never read downstream).
// skipmask path: tile of dead (invalid-token) rows -> return, no write.
// ---------------------------------------------------------------------------
#define HS 40

template<int COMBOS>
__global__ __launch_bounds__(256, COMBOS == 2 ? 3 : 2)
void hgemm_kernel(const __half* __restrict__ Ah, const __half* __restrict__ Al,
                  const __half* __restrict__ Bh, const __half* __restrict__ Bl,
                  const float* __restrict__ bias, float* __restrict__ C,
                  __half* __restrict__ Ch, __half* __restrict__ Cl,
                  int M, int N, int K, int act, int out_split,
                  const float* __restrict__ maxseg,
                  const float* __restrict__ crf,
                  const __half* __restrict__ crh, const __half* __restrict__ crl,
                  const float* __restrict__ skipmask)
{
    extern __shared__ __half hsm[];
    constexpr uint32_t STG_H = (COMBOS == 3) ? 20480u : 15360u;  // halves/stage
    constexpr uint32_t ALO   = 5120u;                            // Al (3-combo)
    constexpr uint32_t BHO   = (COMBOS == 3) ? 10240u : 5120u;   // Bh offset

    const int tid  = threadIdx.x;
    const int wid  = tid >> 5;
    const int lane = tid & 31;
    const int gr   = lane >> 2;
    const int gc   = lane & 3;
    const int lg   = lane >> 3;
    const int lr   = lane & 7;

    // ---- grouped rasterization: groups of 16 M-tiles, rows vary fastest
    const int nbx = gridDim.x, nby = gridDim.y;
    int lin = blockIdx.y * nbx + blockIdx.x;
    const int GRP = 16;
    int grp  = lin / (GRP * nbx);
    int rem  = lin - grp * GRP * nbx;
    int rows = nby - grp * GRP; if (rows > GRP) rows = GRP;
    int by   = grp * GRP + rem % rows;
    int bx   = rem / rows;
    const int row0 = by * 128;
    const int col0 = bx * 128;

    // ---- dead-row tile skip (invalid tokens; prefix mask => whole tile dead)
    if (skipmask != nullptr) {
        if (skipmask[row0] <= 0.0f) return;
    }

    // ---- zero-row tile fast path (uniform branch)
    if (maxseg != nullptr) {
        int bb = row0 >> 10;
        int rloc = row0 & 1023;
        if ((float)rloc > maxseg[bb]) {
            if (!out_split) {
                if (crf == nullptr) return;   // rows never read downstream
                for (int idx = tid * 4; idx < 128 * 128; idx += 256 * 4) {
                    int r = idx >> 7, c = idx & 127;
                    *(float4*)(C + (size_t)(row0 + r) * N + col0 + c) =
                        *(const float4*)(crf + col0 + c);
                }
            } else {
                if (crh == nullptr) return;   // rows never read downstream
                for (int idx = tid * 8; idx < 128 * 128; idx += 256 * 8) {
                    int r = idx >> 7, c = idx & 127;
                    *(uint4*)(Ch + (size_t)(row0 + r) * N + col0 + c) =
                        *(const uint4*)(crh + col0 + c);
                    *(uint4*)(Cl + (size_t)(row0 + r) * N + col0 + c) =
                        *(const uint4*)(crl + col0 + c);
                }
            }
            return;
        }
    }

    const int warp_m = (wid & 3) * 32;
    const int warp_n = (wid >> 2) * 64;
    const uint32_t sbase = smem_u32(hsm);

    const int a_rowoff = (lg & 1) * 8 + lr;
    const int a_koff   = (lg >> 1) * 8;
    const int b_rowoff = (lg >> 1) * 8 + lr;
    const int b_koff   = (lg & 1) * 8;

    float acc[2][8][4];
#pragma unroll
    for (int i = 0; i < 2; i++)
#pragma unroll
        for (int j = 0; j < 8; j++)
#pragma unroll
            for (int r = 0; r < 4; r++) acc[i][j][r] = 0.0f;

    const int nk = K >> 5;
    const int c0i = tid * 2, c1i = tid * 2 + 1;
    const int m0 = c0i >> 2, kc0 = (c0i & 3) * 8;
    const int m1 = c1i >> 2, kc1 = (c1i & 3) * 8;

#define H_LOAD_STAGE(st, k0)                                                     \
    do {                                                                         \
        uint32_t b = sbase + (uint32_t)(st) * STG_H * 2u;                        \
        cp16(b + (uint32_t)(m0 * HS + kc0) * 2u,                                 \
             Ah + (size_t)(row0 + m0) * K + (k0) + kc0);                         \
        cp16(b + (uint32_t)(m1 * HS + kc1) * 2u,                                 \
             Ah + (size_t)(row0 + m1) * K + (k0) + kc1);                         \
        if (COMBOS == 3) {                                                       \
            cp16(b + (ALO + (uint32_t)(m0 * HS + kc0)) * 2u,                     \
                 Al + (size_t)(row0 + m0) * K + (k0) + kc0);                     \
            cp16(b + (ALO + (uint32_t)(m1 * HS + kc1)) * 2u,                     \
                 Al + (size_t)(row0 + m1) * K + (k0) + kc1);                     \
        }                                                                        \
        cp16(b + (BHO + (uint32_t)(m0 * HS + kc0)) * 2u,                         \
             Bh + (size_t)(col0 + m0) * K + (k0) + kc0);                         \
        cp16(b + (BHO + (uint32_t)(m1 * HS + kc1)) * 2u,                         \
             Bh + (size_t)(col0 + m1) * K + (k0) + kc1);                         \
        cp16(b + (BHO + 5120u + (uint32_t)(m0 * HS + kc0)) * 2u,                 \
             Bl + (size_t)(col0 + m0) * K + (k0) + kc0);                         \
        cp16(b + (BHO + 5120u + (uint32_t)(m1 * HS + kc1)) * 2u,                 \
             Bl + (size_t)(col0 + m1) * K + (k0) + kc1);                         \
        asm volatile("cp.async.commit_group;\n");                                \
    } while (0)

    H_LOAD_STAGE(0, 0);

    for (int t = 0; t < nk; t++) {
        const int st = t & 1;
        if (t + 1 < nk) {
            H_LOAD_STAGE((t + 1) & 1, (t + 1) << 5);
            asm volatile("cp.async.wait_group 1;\n");
        } else {
            asm volatile("cp.async.wait_group 0;\n");
        }
        __syncthreads();

        const uint32_t sg = sbase + (uint32_t)st * STG_H * 2u;

#pragma unroll
        for (int ks = 0; ks < 2; ks++) {
            const int kh = ks * 16;
            uint32_t ahf[2][4], alf[2][4];
#pragma unroll
            for (int mt = 0; mt < 2; mt++) {
                uint32_t aaddr = sg + (uint32_t)(
                    (warp_m + mt * 16 + a_rowoff) * HS + kh + a_koff) * 2u;
                ldsm_x4(ahf[mt], aaddr);
                if (COMBOS == 3)
                    ldsm_x4(alf[mt], aaddr + ALO * 2u);
            }
#pragma unroll
            for (int p = 0; p < 4; p++) {
                uint32_t baddr = sg + BHO * 2u + (uint32_t)(
                    (warp_n + p * 16 + b_rowoff) * HS + kh + b_koff) * 2u;
                uint32_t bhf[4], blf[4];
                ldsm_x4(bhf, baddr);
                ldsm_x4(blf, baddr + 5120u * 2u);
#pragma unroll
                for (int q = 0; q < 2; q++) {
                    const int nt = p * 2 + q;
                    uint32_t bh0 = bhf[q * 2], bh1 = bhf[q * 2 + 1];
                    uint32_t bl0 = blf[q * 2], bl1 = blf[q * 2 + 1];
#pragma unroll
                    for (int mt = 0; mt < 2; mt++) {
                        float* c = acc[mt][nt];
                        mma_f16(c, ahf[mt][0], ahf[mt][1], ahf[mt][2], ahf[mt][3], bh0, bh1);
                        mma_f16(c, ahf[mt][0], ahf[mt][1], ahf[mt][2], ahf[mt][3], bl0, bl1);
                        if (COMBOS == 3)
                            mma_f16(c, alf[mt][0], alf[mt][1], alf[mt][2], alf[mt][3], bh0, bh1);
                    }
                }
            }
        }
        __syncthreads();
    }

#pragma unroll
    for (int mt = 0; mt < 2; mt++) {
        const int r0 = row0 + warp_m + mt * 16 + gr;
#pragma unroll
        for (int nt = 0; nt < 8; nt++) {
            const int cc = col0 + warp_n + nt * 8 + 2 * gc;
            float b0v = bias[cc], b1v = bias[cc + 1];
            float v0 = acc[mt][nt][0] * WSCALE + b0v;
            float v1 = acc[mt][nt][1] * WSCALE + b1v;
            float v2 = acc[mt][nt][2] * WSCALE + b0v;
            float v3 = acc[mt][nt][3] * WSCALE + b1v;
            if (act == 1) {
                v0 = gelu_f(v0); v1 = gelu_f(v1);
                v2 = gelu_f(v2); v3 = gelu_f(v3);
            }
            if (!out_split) {
                *(float2*)(C + (size_t)r0 * N + cc)       = make_float2(v0, v1);
                *(float2*)(C + (size_t)(r0 + 8) * N + cc) = make_float2(v2, v3);
            } else {
                __half h0, l0, h1, l1;
                hsplit(v0, h0, l0); hsplit(v1, h1, l1);
                *(__half2*)(Ch + (size_t)r0 * N + cc) = __halves2half2(h0, h1);
                *(__half2*)(Cl + (size_t)r0 * N + cc) = __halves2half2(l0, l1);
                hsplit(v2, h0, l0); hsplit(v3, h1, l1);
                *(__half2*)(Ch + (size_t)(r0 + 8) * N + cc) = __halves2half2(h0, h1);
                *(__half2*)(Cl + (size_t)(r0 + 8) * N + cc) = __halves2half2(l0, l1);
            }
        }
    }
}

// ---------------------------------------------------------------------------
// Tensor-core flash attention (3-combo fp16, ldmatrix, trans-V).
// Q-tiles of invalid tokens (prefix mask) are dead -> early return.
// Mode 1: fully-masked key tiles skipped (contribution exactly 0).
// ---------------------------------------------------------------------------
#define HST 72
#define ATT_SMEM_BYTES (8 * 64 * HST * 2 + 64 * 4)

__global__ __launch_bounds__(128)
void attn_mma_kernel(const __half* __restrict__ qkvh, const __half* __restrict__ qkvl,
                     const float* __restrict__ masks,
                     int mode, __half* __restrict__ oh, __half* __restrict__ ol)
{
    extern __shared__ __half hs[];
    __half* Qh  = hs;
    __half* Ql  = Qh  + 64 * HST;
    __half* Kh  = Ql  + 64 * HST;
    __half* Kl  = Kh  + 64 * HST;
    __half* Vh  = Kl  + 64 * HST;
    __half* Vl  = Vh  + 64 * HST;
    __half* Psh = Vl  + 64 * HST;
    __half* Psl = Psh + 64 * HST;
    float*  mb  = (float*)(Psl + 64 * HST);

    const uint32_t sQh = smem_u32(Qh), sQl = smem_u32(Ql);
    const uint32_t sKh = smem_u32(Kh), sKl = smem_u32(Kl);
    const uint32_t sVh = smem_u32(Vh), sVl = smem_u32(Vl);
    const uint32_t sPh = smem_u32(Psh), sPl = smem_u32(Psl);

    const int tid  = threadIdx.x;
    const int wid  = tid >> 5;
    const int lane = tid & 31;
    const int gr   = lane >> 2;
    const int gc   = lane & 3;
    const int lg   = lane >> 3;
    const int lr   = lane & 7;
    const int q0   = blockIdx.x * 64;
    const int b    = blockIdx.y >> 4;
    const int h    = blockIdx.y & 15;
    const size_t qbase = (size_t)b * SS * QKVN + (size_t)h * HDIM;
    const size_t obase = (size_t)b * SS * DD + (size_t)h * HDIM;
    const int q0w = wid * 16;

    // dead q-tile skip: invalid queries never influence the final output
    if (masks[b * SS + q0] <= 0.0f) return;

    const int a_ro = (lg & 1) * 8 + lr;
    const int a_ko = (lg >> 1) * 8;
    const int b_ro = (lg >> 1) * 8 + lr;
    const int b_ko = (lg & 1) * 8;
    const int v_ko = (lg & 1) * 8 + lr;
    const int v_do = (lg >> 1) * 8;

    for (int idx = tid; idx < 512; idx += 128) {
        int r = idx >> 3, c8 = (idx & 7) << 3;
        uint32_t soff = (uint32_t)(r * HST + c8) * 2u;
        cp16(sQh + soff, qkvh + qbase + (size_t)(q0 + r) * QKVN + c8);
        cp16(sQl + soff, qkvl + qbase + (size_t)(q0 + r) * QKVN + c8);
    }
    asm volatile("cp.async.commit_group;\n");

    float mrow[2] = {-1e30f, -1e30f};
    float lrow[2] = {0.0f, 0.0f};
    float Oacc[8][4];
#pragma unroll
    for (int i = 0; i < 8; i++)
#pragma unroll
        for (int j = 0; j < 4; j++) Oacc[i][j] = 0.0f;

    for (int t = 0; t < 16; t++) {
        const int k0 = t * 64;
        if (mode == 1 && masks[b * SS + k0] <= 0.0f) continue;

        for (int idx = tid; idx < 512; idx += 128) {
            int r = idx >> 3, c8 = (idx & 7) << 3;
            uint32_t soff = (uint32_t)(r * HST + c8) * 2u;
            size_t kg = qbase + 1024 + (size_t)(k0 + r) * QKVN + c8;
            size_t vg = qbase + 2048 + (size_t)(k0 + r) * QKVN + c8;
            cp16(sKh + soff, qkvh + kg);
            cp16(sKl + soff, qkvl + kg);
            cp16(sVh + soff, qkvh + vg);
            cp16(sVl + soff, qkvl + vg);
        }
        asm volatile("cp.async.commit_group;\n");
        if (tid < 64) {
            float mv = masks[b * SS + k0 + tid];
            mb[tid] = (mode == 0) ? mv : (mv > 0.0f ? 0.0f : -1e9f);
        }
        asm volatile("cp.async.wait_group 0;\n");
        __syncthreads();

        float S[8][4];
#pragma unroll
        for (int i = 0; i < 8; i++)
#pragma unroll
            for (int j = 0; j < 4; j++) S[i][j] = 0.0f;

#pragma unroll
        for (int kh = 0; kh < 64; kh += 16) {
            uint32_t qhf[4], qlf[4];
            {
                uint32_t qaddr = (uint32_t)((q0w + a_ro) * HST + kh + a_ko) * 2u;
                ldsm_x4(qhf, sQh + qaddr);
                ldsm_x4(qlf, sQl + qaddr);
            }
#pragma unroll
            for (int p = 0; p < 4; p++) {
                uint32_t kaddr = (uint32_t)((p * 16 + b_ro) * HST + kh + b_ko) * 2u;
                uint32_t khf[4], klf[4];
                ldsm_x4(khf, sKh + kaddr);
                ldsm_x4(klf, sKl + kaddr);
#pragma unroll
                for (int q = 0; q < 2; q++) {
                    const int nt = p * 2 + q;
                    uint32_t kh0 = khf[q * 2], kh1 = khf[q * 2 + 1];
                    uint32_t kl0 = klf[q * 2], kl1 = klf[q * 2 + 1];
                    mma_f16(S[nt], qhf[0], qhf[1], qhf[2], qhf[3], kh0, kh1);
                    mma_f16(S[nt], qhf[0], qhf[1], qhf[2], qhf[3], kl0, kl1);
                    mma_f16(S[nt], qlf[0], qlf[1], qlf[2], qlf[3], kh0, kh1);
                }
            }
        }

        float rmax[2] = {-1e30f, -1e30f};
#pragma unroll
        for (int nt = 0; nt < 8; nt++) {
            float m0 = mb[nt * 8 + 2 * gc];
            float m1 = mb[nt * 8 + 2 * gc + 1];
            S[nt][0] = S[nt][0] * 0.125f + m0;
            S[nt][1] = S[nt][1] * 0.125f + m1;
            S[nt][2] = S[nt][2] * 0.125f + m0;
            S[nt][3] = S[nt][3] * 0.125f + m1;
            rmax[0] = fmaxf(rmax[0], fmaxf(S[nt][0], S[nt][1]));
            rmax[1] = fmaxf(rmax[1], fmaxf(S[nt][2], S[nt][3]));
        }
#pragma unroll
        for (int sh = 1; sh < 4; sh <<= 1) {
            rmax[0] = fmaxf(rmax[0], __shfl_xor_sync(0xffffffffu, rmax[0], sh));
            rmax[1] = fmaxf(rmax[1], __shfl_xor_sync(0xffffffffu, rmax[1], sh));
        }
        float mnew0 = fmaxf(mrow[0], rmax[0]);
        float mnew1 = fmaxf(mrow[1], rmax[1]);
        float scl0 = __expf(mrow[0] - mnew0);
        float scl1 = __expf(mrow[1] - mnew1);
        float rsum[2] = {0.0f, 0.0f};
#pragma unroll
        for (int nt = 0; nt < 8; nt++) {
            S[nt][0] = __expf(S[nt][0] - mnew0);
            S[nt][1] = __expf(S[nt][1] - mnew0);
            S[nt][2] = __expf(S[nt][2] - mnew1);
            S[nt][3] = __expf(S[nt][3] - mnew1);
            rsum[0] += S[nt][0] + S[nt][1];
            rsum[1] += S[nt][2] + S[nt][3];
        }
#pragma unroll
        for (int sh = 1; sh < 4; sh <<= 1) {
            rsum[0] += __shfl_xor_sync(0xffffffffu, rsum[0], sh);
            rsum[1] += __shfl_xor_sync(0xffffffffu, rsum[1], sh);
        }
        lrow[0] = lrow[0] * scl0 + rsum[0];
        lrow[1] = lrow[1] * scl1 + rsum[1];
        mrow[0] = mnew0; mrow[1] = mnew1;
#pragma unroll
        for (int dt = 0; dt < 8; dt++) {
            Oacc[dt][0] *= scl0; Oacc[dt][1] *= scl0;
            Oacc[dt][2] *= scl1; Oacc[dt][3] *= scl1;
        }

        __syncwarp();
#pragma unroll
        for (int nt = 0; nt < 8; nt++) {
            int c0 = nt * 8 + 2 * gc;
            __half h0, l0, h1, l1;
            hsplit(S[nt][0], h0, l0); hsplit(S[nt][1], h1, l1);
            *(__half2*)(Psh + (q0w + gr) * HST + c0) = __halves2half2(h0, h1);
            *(__half2*)(Psl + (q0w + gr) * HST + c0) = __halves2half2(l0, l1);
            hsplit(S[nt][2], h0, l0); hsplit(S[nt][3], h1, l1);
            *(__half2*)(Psh + (q0w + gr + 8) * HST + c0) = __halves2half2(h0, h1);
            *(__half2*)(Psl + (q0w + gr + 8) * HST + c0) = __halves2half2(l0, l1);
        }
        __syncwarp();

#pragma unroll
        for (int kh = 0; kh < 64; kh += 16) {
            uint32_t phf[4], plf[4];
            {
                uint32_t paddr = (uint32_t)((q0w + a_ro) * HST + kh + a_ko) * 2u;
                ldsm_x4(phf, sPh + paddr);
                ldsm_x4(plf, sPl + paddr);
            }
#pragma unroll
            for (int p = 0; p < 4; p++) {
                const int d0 = p * 16;
                uint32_t vaddr = (uint32_t)((kh + v_ko) * HST + d0 + v_do) * 2u;
                uint32_t vhf[4], vlf[4];
                ldsm_x4_t(vhf, sVh + vaddr);
                ldsm_x4_t(vlf, sVl + vaddr);
#pragma unroll
                for (int q = 0; q < 2; q++) {
                    const int dt = p * 2 + q;
                    uint32_t vh0 = vhf[q * 2], vh1 = vhf[q * 2 + 1];
                    uint32_t vl0 = vlf[q * 2], vl1 = vlf[q * 2 + 1];
                    mma_f16(Oacc[dt], phf[0], phf[1], phf[2], phf[3], vh0, vh1);
                    mma_f16(Oacc[dt], phf[0], phf[1], phf[2], phf[3], vl0, vl1);
                    mma_f16(Oacc[dt], plf[0], plf[1], plf[2], plf[3], vh0, vh1);
                }
            }
        }
        __syncthreads();
    }

    float inv0 = 1.0f / lrow[0];
    float inv1 = 1.0f / lrow[1];
    const int r0 = q0 + q0w + gr;
#pragma unroll
    for (int dt = 0; dt < 8; dt++) {
        int col = dt * 8 + 2 * gc;
        __half h0, l0, h1, l1;
        hsplit(Oacc[dt][0] * inv0, h0, l0);
        hsplit(Oacc[dt][1] * inv0, h1, l1);
        *(__half2*)(oh + obase + (size_t)r0 * DD + col) = __halves2half2(h0, h1);
        *(__half2*)(ol + obase + (size_t)r0 * DD + col) = __halves2half2(l0, l1);
        hsplit(Oacc[dt][2] * inv1, h0, l0);
        hsplit(Oacc[dt][3] * inv1, h1, l1);
        *(__half2*)(oh + obase + (size_t)(r0 + 8) * DD + col) = __halves2half2(h0, h1);
        *(__half2*)(ol + obase + (size_t)(r0 + 8) * DD + col) = __halves2half2(l0, l1);
    }
}

// ---------------------------------------------------------------------------
// Transpose + scale x64 + fp16 split, 64x64 tiles, vectorized.
// ---------------------------------------------------------------------------
__device__ __forceinline__ void trans_split_tile(
    const float* W, __half* Wh, __half* Wl, int Kd, int Nd,
    int n0, int k0, float (*t)[65])
{
    const int tx = threadIdx.x & 15;
    const int ty = threadIdx.x >> 4;

#pragma unroll
    for (int r = ty; r < 64; r += 16) {
        float4 v = *(const float4*)(W + (size_t)(k0 + r) * Nd + n0 + tx * 4);
        t[r][tx * 4 + 0] = v.x;
        t[r][tx * 4 + 1] = v.y;
        t[r][tx * 4 + 2] = v.z;
        t[r][tx * 4 + 3] = v.w;
    }
    __syncthreads();

#pragma unroll
    for (int n = ty; n < 64; n += 16) {
        float a0 = t[tx * 4 + 0][n] * 64.0f;
        float a1 = t[tx * 4 + 1][n] * 64.0f;
        float a2 = t[tx * 4 + 2][n] * 64.0f;
        float a3 = t[tx * 4 + 3][n] * 64.0f;
        __half hv[4], lv[4];
        hsplit(a0, hv[0], lv[0]); hsplit(a1, hv[1], lv[1]);
        hsplit(a2, hv[2], lv[2]); hsplit(a3, hv[3], lv[3]);
        *(uint2*)(Wh + (size_t)(n0 + n) * Kd + k0 + tx * 4) = *(uint2*)hv;
        *(uint2*)(Wl + (size_t)(n0 + n) * Kd + k0 + tx * 4) = *(uint2*)lv;
    }
}

__global__ __launch_bounds__(256)
void trans_split_h_kernel(const float* __restrict__ W,
                          __half* __restrict__ Wh, __half* __restrict__ Wl,
                          int Kd, int Nd)
{
    __shared__ float t[64][65];
    trans_split_tile(W, Wh, Wl, Kd, Nd, blockIdx.x * 64, blockIdx.y * 64, t);
}

// merged variant: 4 same-shape 1024x1024 weights, z selects source
__global__ __launch_bounds__(256)
void trans_split4_kernel(const float* __restrict__ W0, const float* __restrict__ W1,
                         const float* __restrict__ W2, const float* __restrict__ W3,
                         __half* __restrict__ H0, __half* __restrict__ L0,
                         __half* __restrict__ H1, __half* __restrict__ L1,
                         __half* __restrict__ H2, __half* __restrict__ L2,
                         __half* __restrict__ H3, __half* __restrict__ L3)
{
    __shared__ float t[64][65];
    const float* W; __half* Wh; __half* Wl;
    switch (blockIdx.z) {
        case 0: W = W0; Wh = H0; Wl = L0; break;
        case 1: W = W1; Wh = H1; Wl = L1; break;
        case 2: W = W2; Wh = H2; Wl = L2; break;
        default: W = W3; Wh = H3; Wl = L3; break;
    }
    trans_split_tile(W, Wh, Wl, DD, DD, blockIdx.x * 64, blockIdx.y * 64, t);
}

// ---------------------------------------------------------------------------
// Elementwise fp16 split, vectorized x4
// ---------------------------------------------------------------------------
__global__ __launch_bounds__(256)
void split_h_kernel(const float* __restrict__ a, __half* __restrict__ ah,
                    __half* __restrict__ al, int n)
{
    int i = (blockIdx.x * 256 + threadIdx.x) * 4;
    if (i < n) {
        float4 v = *(const float4*)(a + i);
        __half hv[4], lv[4];
        hsplit(v.x, hv[0], lv[0]); hsplit(v.y, hv[1], lv[1]);
        hsplit(v.z, hv[2], lv[2]); hsplit(v.w, hv[3], lv[3]);
        *(uint2*)(ah + i) = *(uint2*)hv;
        *(uint2*)(al + i) = *(uint2*)lv;
    }
}

__global__ __launch_bounds__(256)
void concat_bias_kernel(const float* __restrict__ bq, const float* __restrict__ bk,
                        const float* __restrict__ bv, float* __restrict__ bqkv)
{
    int i = blockIdx.x * 256 + threadIdx.x;
    if (i < QKVN) {
        float v = (i < 1024) ? bq[i] : ((i < 2048) ? bk[i - 1024] : bv[i - 2048]);
        bqkv[i] = v;
    }
}

// const row 1: c1 = gelu(bp1)
__global__ __launch_bounds__(256)
void const_row1_kernel(const float* __restrict__ bp1, float* __restrict__ c1f,
                       __half* __restrict__ c1h, __half* __restrict__ c1l)
{
    int i = blockIdx.x * 256 + threadIdx.x;
    if (i < HID) {
        float v = gelu_f(bp1[i]);
        c1f[i] = v;
        __half h, l;
        hsplit(v, h, l);
        c1h[i] = h; c1l[i] = l;
    }
}

// const row 2: c2 = c1 @ P2 + bp2 (fp32 GEMV over split-transposed P2)
__global__ __launch_bounds__(256)
void const_row2_kernel(const float* __restrict__ c1f,
                       const __half* __restrict__ p2h, const __half* __restrict__ p2l,
                       const float* __restrict__ bp2, float* __restrict__ c2f)
{
    int n = blockIdx.x * 8 + (threadIdx.x >> 5);
    int lane = threadIdx.x & 31;
    const __half* rh = p2h + (size_t)n * HID;
    const __half* rl = p2l + (size_t)n * HID;
    float acc = 0.0f;
    for (int k = lane; k < HID; k += 32)
        acc += c1f[k] * (__half2float(rh[k]) + __half2float(rl[k]));
#pragma unroll
    for (int m = 16; m; m >>= 1) acc += __shfl_xor_sync(0xffffffffu, acc, m);
    if (lane == 0) c2f[n] = acc * WSCALE + bp2[n];
}

// ---------------------------------------------------------------------------
// out = LayerNorm(a + b) * g + beta ; fp16 split out; dead rows skipped
// ---------------------------------------------------------------------------
__global__ __launch_bounds__(256)
void add_ln_kernel(const float* __restrict__ a, const float* __restrict__ b2,
                   const float* __restrict__ g, const float* __restrict__ beta,
                   float* __restrict__ out,
                   __half* __restrict__ outh, __half* __restrict__ outl,
                   const float* __restrict__ vmask)
{
    const int row = blockIdx.x;
    if (vmask[row] <= 0.0f) return;
    const size_t off = (size_t)row * DD;
    const int t = threadIdx.x;
    __shared__ float r1[256], r2[256];

    float vloc[4];
    float s = 0.0f, s2 = 0.0f;
#pragma unroll
    for (int i = 0; i < 4; i++) {
        int d = t + i * 256;
        float vv = a[off + d] + b2[off + d];
        vloc[i] = vv;
        s += vv; s2 += vv * vv;
    }
    r1[t] = s; r2[t] = s2;
    __syncthreads();
    for (int o2 = 128; o2 > 0; o2 >>= 1) {
        if (t < o2) { r1[t] += r1[t + o2]; r2[t] += r2[t + o2]; }
        __syncthreads();
    }
    float mean = r1[0] * (1.0f / DD);
    float var  = r2[0] * (1.0f / DD) - mean * mean;
    float inv  = rsqrtf(var + 1e-5f);
#pragma unroll
    for (int i = 0; i < 4; i++) {
        int d = t + i * 256;
        float vv = (vloc[i] - mean) * inv * g[d] + beta[d];
        out[off + d] = vv;
        __half h, l;
        hsplit(vv, h, l);
        outh[off + d] = h;
        outl[off + d] = l;
    }
}

__global__ __launch_bounds__(256)
void score_kernel(const float* __restrict__ feat, const float* __restrict__ Ws,
                  const float* __restrict__ bs, float* __restrict__ sbuf)
{
    int token = blockIdx.x * 8 + (threadIdx.x >> 5);
    int lane  = threadIdx.x & 31;
    const float* f = feat + (size_t)token * DD;
    float acc = 0.0f;
    for (int i = lane; i < DD; i += 32) acc += f[i] * Ws[i];
#pragma unroll
    for (int m = 16; m; m >>= 1) acc += __shfl_xor_sync(0xffffffffu, acc, m);
    if (lane == 0) sbuf[token] = 1.0f / (1.0f + expf(-(acc + bs[0])));
}

__global__ __launch_bounds__(1024)
void scan_kernel(const float* __restrict__ sbuf, const float* __restrict__ masks,
                 float* __restrict__ svbuf, int* __restrict__ segbuf,
                 float* __restrict__ maxseg)
{
    const int b = blockIdx.x;
    const int t = threadIdx.x;
    __shared__ float sc[SS];
    __shared__ float mr[SS];

    float valid = masks[b * SS + t];
    float sv = (valid > 0.0f) ? sbuf[b * SS + t] : 0.0f;
    svbuf[b * SS + t] = sv;
    sc[t] = sv;
    __syncthreads();
    for (int off = 1; off < SS; off <<= 1) {
        float vprev = (t >= off) ? sc[t - off] : 0.0f;
        __syncthreads();
        sc[t] += vprev;
        __syncthreads();
    }
    float c = floorf(sc[t]);
    int seg = (int)c;
    seg = seg < 0 ? 0 : (seg > SS - 1 ? SS - 1 : seg);
    segbuf[b * SS + t] = seg;

    mr[t] = (valid > 0.0f) ? c : -1.0f;
    __syncthreads();
    for (int off = 512; off > 0; off >>= 1) {
        if (t < off) mr[t] = fmaxf(mr[t], mr[t + off]);
        __syncthreads();
    }
    if (t == 0) maxseg[b] = mr[0];
}

// ---------------------------------------------------------------------------
// pooled[b,g,:] = segment-sum; blocks in fully-skipped P1 tiles are dead
// ---------------------------------------------------------------------------
__global__ __launch_bounds__(256)
void pool_kernel(const float* __restrict__ x, const float* __restrict__ svbuf,
                 const int* __restrict__ segbuf,
                 __half* __restrict__ ph, __half* __restrict__ pl,
                 const float* __restrict__ maxseg)
{
    const int g = blockIdx.x;
    const int b = blockIdx.y;
    if ((float)(g & ~127) > maxseg[b]) return;

    const int* seg = segbuf + b * SS;

    int lo = 0, hi = SS;
    while (lo < hi) { int mid = (lo + hi) >> 1; if (seg[mid] < g) lo = mid + 1; else hi = mid; }
    int beg = lo;
    lo = beg; hi = SS;
    while (lo < hi) { int mid = (lo + hi) >> 1; if (seg[mid] < g + 1) lo = mid + 1; else hi = mid; }
    int end = lo;

    const int t = threadIdx.x;
    float acc[4] = {0.0f, 0.0f, 0.0f, 0.0f};
    for (int s = beg; s < end; s++) {
        float w = svbuf[b * SS + s];
        const float* xr = x + ((size_t)b * SS + s) * DD;
#pragma unroll
        for (int i = 0; i < 4; i++) acc[i] += xr[t + i * 256] * w;
    }
    size_t rbase = ((size_t)b * SS + g) * DD;
#pragma unroll
    for (int i = 0; i < 4; i++) {
        __half h, l;
        hsplit(acc[i], h, l);
        ph[rbase + t + i * 256] = h;
        pl[rbase + t + i * 256] = l;
    }
}

__global__ __launch_bounds__(1024)
void mask_kernel(const float* __restrict__ maxseg, float* __restrict__ outmask)
{
    const int b = blockIdx.x;
    const int t = threadIdx.x;
    outmask[b * SS + t] = ((float)t <= maxseg[b]) ? 1.0f : 0.0f;
}

// ---------------------------------------------------------------------------
// Host side
// ---------------------------------------------------------------------------
static void* sym_addr(const void* sym) {
    void* p = nullptr;
    cudaGetSymbolAddress(&p, sym);
    return p;
}

#define H_SMEM3 (2 * 20480 * 2)
#define H_SMEM2 (2 * 15360 * 2)

static void launch_hgemm(const __half* Ah, const __half* Al,
                         const __half* Bh, const __half* Bl,
                         const float* bias, float* C,
                         __half* Ch, __half* Cl,
                         int M, int N, int K, int act, int out_split,
                         int combos,
                         const float* maxseg = nullptr,
                         const float* crf = nullptr,
                         const __half* crh = nullptr,
                         const __half* crl = nullptr,
                         const float* skipmask = nullptr) {
    dim3 grid(N / 128, M / 128);
    if (combos == 3)
        hgemm_kernel<3><<<grid, 256, H_SMEM3>>>(Ah, Al, Bh, Bl, bias, C,
                                                Ch, Cl, M, N, K, act, out_split,
                                                maxseg, crf, crh, crl, skipmask);
    else
        hgemm_kernel<2><<<grid, 256, H_SMEM2>>>(Ah, Al, Bh, Bl, bias, C,
                                                Ch, Cl, M, N, K, act, out_split,
                                                maxseg, crf, crh, crl, skipmask);
}

extern "C" void kernel_launch(void* const* d_in, const int* in_sizes, int n_in,
                              void* d_out, int out_size)
{
    (void)in_sizes; (void)n_in;
    const float* x     = (const float*)d_in[0];
    const float* masks = (const float*)d_in[1];
    const float* Wq  = (const float*)d_in[2];
    const float* bq  = (const float*)d_in[3];
    const float* Wk  = (const float*)d_in[4];
    const float* bk  = (const float*)d_in[5];
    const float* Wv  = (const float*)d_in[6];
    const float* bv  = (const float*)d_in[7];
    const float* Wo  = (const float*)d_in[8];
    const float* bo  = (const float*)d_in[9];
    const float* g1  = (const float*)d_in[10];
    const float* be1 = (const float*)d_in[11];
    const float* g2  = (const float*)d_in[12];
    const float* be2 = (const float*)d_in[13];
    const float* W1  = (const float*)d_in[14];
    const float* bf1 = (const float*)d_in[15];
    const float* W2  = (const float*)d_in[16];
    const float* bf2 = (const float*)d_in[17];
    const float* Ws  = (const float*)d_in[18];
    const float* bs  = (const float*)d_in[19];
    const float* P1  = (const float*)d_in[20];
    const float* bp1 = (const float*)d_in[21];
    const float* P2  = (const float*)d_in[22];
    const float* bp2 = (const float*)d_in[23];

    float* out = (float*)d_out;
    (void)out_size;

    cudaFuncSetAttribute(attn_mma_kernel,
                         cudaFuncAttributeMaxDynamicSharedMemorySize,
                         ATT_SMEM_BYTES);
    cudaFuncSetAttribute(hgemm_kernel<3>,
                         cudaFuncAttributeMaxDynamicSharedMemorySize, H_SMEM3);
    cudaFuncSetAttribute(hgemm_kernel<2>,
                         cudaFuncAttributeMaxDynamicSharedMemorySize, H_SMEM2);

    float* ob    = (float*)sym_addr(g_o);
    float* hb    = (float*)sym_addr(g_h);
    float* featb = (float*)sym_addr(g_feat);
    float* feat2b= (float*)sym_addr(g_feat2);
    float* sb    = (float*)sym_addr(g_s);
    float* svb   = (float*)sym_addr(g_sv);
    int*   segb  = (int*)sym_addr(g_seg);
    float* msb   = (float*)sym_addr(g_maxseg);
    float* bqkvb = (float*)sym_addr(g_bqkv);
    float* c1f   = (float*)sym_addr(g_c1f);
    float* c2f   = (float*)sym_addr(g_c2f);

    __half* c1h = (__half*)sym_addr(g_c1h);
    __half* c1l = (__half*)sym_addr(g_c1l);
    __half* qkvh = (__half*)sym_addr(g_qkvh);
    __half* qkvl = (__half*)sym_addr(g_qkvl);
    __half* xh  = (__half*)sym_addr(g_xh);
    __half* xl  = (__half*)sym_addr(g_xl);
    __half* fh  = (__half*)sym_addr(g_fh);
    __half* fl  = (__half*)sym_addr(g_fl);
    __half* ath = (__half*)sym_addr(g_ath);
    __half* atl = (__half*)sym_addr(g_atl);
    __half* hh  = (__half*)sym_addr(g_hh);
    __half* hl  = (__half*)sym_addr(g_hl);
    __half* ffh = (__half*)sym_addr(g_ffh);
    __half* ffl = (__half*)sym_addr(g_ffl);
    __half* plh = (__half*)sym_addr(g_plh);
    __half* pll = (__half*)sym_addr(g_pll);
    __half* phh = (__half*)sym_addr(g_phh);
    __half* phl = (__half*)sym_addr(g_phl);

    __half* wqkvh = (__half*)sym_addr(g_wqkvh);
    __half* wqkvl = (__half*)sym_addr(g_wqkvl);
    __half* woh = (__half*)sym_addr(g_woh);
    __half* wol = (__half*)sym_addr(g_wol);
    __half* w1h = (__half*)sym_addr(g_w1h);
    __half* w1l = (__half*)sym_addr(g_w1l);
    __half* w2h = (__half*)sym_addr(g_w2h);
    __half* w2l = (__half*)sym_addr(g_w2l);
    __half* p1h = (__half*)sym_addr(g_p1h);
    __half* p1l = (__half*)sym_addr(g_p1l);
    __half* p2h = (__half*)sym_addr(g_p2h);
    __half* p2l = (__half*)sym_addr(g_p2l);

    // ---- weight prep: merged 4x 1024^2 transpose-split + the rest ----
    trans_split4_kernel<<<dim3(DD / 64, DD / 64, 4), 256>>>(
        Wq, Wk, Wv, Wo,
        wqkvh, wqkvl,
        wqkvh + DD * DD, wqkvl + DD * DD,
        wqkvh + 2 * DD * DD, wqkvl + 2 * DD * DD,
        woh, wol);
    trans_split_h_kernel<<<dim3(FF / 64, DD / 64), 256>>>(W1, w1h, w1l, DD, FF);
    trans_split_h_kernel<<<dim3(DD / 64, FF / 64), 256>>>(W2, w2h, w2l, FF, DD);
    trans_split_h_kernel<<<dim3(HID / 64, DD / 64), 256>>>(P1, p1h, p1l, DD, HID);
    trans_split_h_kernel<<<dim3(HID / 64, HID / 64), 256>>>(P2, p2h, p2l, HID, HID);
    concat_bias_kernel<<<(QKVN + 255) / 256, 256>>>(bq, bk, bv, bqkvb);
    split_h_kernel<<<(TOK * DD / 4 + 255) / 256, 256>>>(x, xh, xl, TOK * DD);
    const_row1_kernel<<<(HID + 255) / 256, 256>>>(bp1, c1f, c1h, c1l);
    const_row2_kernel<<<HID / 8, 256>>>(c1f, p2h, p2l, bp2, c2f);

    // ---- encoder layer, applied twice (3 combos: exact path) ----
    const __half* inh = xh;
    const __half* inl = xl;
    const float* enc_in = x;
    float* enc_out = featb;
    for (int pass = 0; pass < 2; pass++) {
        int mode = pass;
        const float* qkv_skip = (pass == 0) ? nullptr : masks;
        launch_hgemm(inh, inl, wqkvh, wqkvl, bqkvb, nullptr, qkvh, qkvl,
                     TOK, QKVN, DD, 0, 1, 3,
                     nullptr, nullptr, nullptr, nullptr, qkv_skip);
        attn_mma_kernel<<<dim3(SS / 64, BB * HH), 128, ATT_SMEM_BYTES>>>(
            qkvh, qkvl, masks, mode, ath, atl);
        launch_hgemm(ath, atl, woh, wol, bo, ob, nullptr, nullptr,
                     TOK, DD, DD, 0, 0, 3,
                     nullptr, nullptr, nullptr, nullptr, masks);
        add_ln_kernel<<<TOK, 256>>>(enc_in, ob, g1, be1, hb, hh, hl, masks);
        launch_hgemm(hh, hl, w1h, w1l, bf1, nullptr, ffh, ffl,
                     TOK, FF, DD, 1, 1, 3,
                     nullptr, nullptr, nullptr, nullptr, masks);
        launch_hgemm(ffh, ffl, w2h, w2l, bf2, ob, nullptr, nullptr,
                     TOK, DD, FF, 0, 0, 3,
                     nullptr, nullptr, nullptr, nullptr, masks);
        add_ln_kernel<<<TOK, 256>>>(hb, ob, g2, be2, enc_out, fh, fl, masks);
        enc_in = featb;
        enc_out = feat2b;
        inh = fh; inl = fl;
    }

    // ---- importance scores, cumsum segmentation ----
    score_kernel<<<TOK / 8, 256>>>(feat2b, Ws, bs, sb);
    scan_kernel<<<BB, 1024>>>(sb, masks, svb, segb, msb);

    // ---- weighted segment-sum pooling of original x (split fp16 output) ----
    pool_kernel<<<dim3(SS, BB), 256>>>(x, svb, segb, plh, pll, msb);

    // ---- projector: 2-combo compact-smem fp16 + zero-row tile skip ----
    // P1 skipped tiles write NOTHING (their ph rows are provably never read:
    // the identically-partitioned P2 row-tiles are skipped by the same predicate)
    launch_hgemm(plh, pll, p1h, p1l, bp1, nullptr, phh, phl,
                 TOK, HID, DD, 1, 1, 2, msb, nullptr, nullptr, nullptr);
    launch_hgemm(phh, phl, p2h, p2l, bp2, out, nullptr, nullptr,
                 TOK, HID, HID, 0, 0, 2, msb, c2f, nullptr, nullptr);

    // ---- new_mask appended after the [B,S,HID] output ----
    mask_kernel<<<BB, 1024>>>(msb, out + (size_t)TOK * HID);
}

// round 17
// speedup vs baseline: 1.0842x; 1.0842x over previous
#include <cuda_runtime.h>
#include <cuda_fp16.h>
#include <cstdint>
#include <math.h>

// ---------------------------------------------------------------------------
// Problem constants
// ---------------------------------------------------------------------------
#define BB 4
#define SS 1024
#define DD 1024
#define HH 16
#define HDIM 64
#define FF 2048
#define HID 4096
#define TOK (BB*SS)          // 4096 tokens
#define QKVN 3072
#define WSCALE (1.0f/64.0f)  // weights pre-scaled by 64 (fp16 subnormal guard)

// ---------------------------------------------------------------------------
// Scratch (__device__ globals; no allocation allowed)
// ---------------------------------------------------------------------------
__device__ float g_o   [TOK*DD];
__device__ float g_h   [TOK*DD];
__device__ float g_feat[TOK*DD];
__device__ float g_feat2[TOK*DD];
__device__ float g_s   [TOK];
__device__ float g_sv  [TOK];
__device__ int   g_seg [TOK];
__device__ float g_maxseg[BB];
__device__ float g_bqkv[QKVN];

// const rows for zero-pooled-row fast path
__device__ float  g_c1f[HID];
__device__ __half g_c1h[HID], g_c1l[HID];
__device__ float  g_c2f[HID];

// fp16 split activations
__device__ __half g_qkvh[TOK*QKVN], g_qkvl[TOK*QKVN];
__device__ __half g_xh[TOK*DD],    g_xl[TOK*DD];
__device__ __half g_fh[TOK*DD],    g_fl[TOK*DD];
__device__ __half g_ath[TOK*DD],   g_atl[TOK*DD];
__device__ __half g_hh[TOK*DD],    g_hl[TOK*DD];
__device__ __half g_ffh[TOK*FF],   g_ffl[TOK*FF];
__device__ __half g_plh[TOK*DD],   g_pll[TOK*DD];
__device__ __half g_phh[TOK*HID],  g_phl[TOK*HID];

// fp16 split weights [N,K] K-contiguous, pre-scaled x64
__device__ __half g_wqkvh[QKVN*DD], g_wqkvl[QKVN*DD];
__device__ __half g_woh[DD*DD],     g_wol[DD*DD];
__device__ __half g_w1h[FF*DD],     g_w1l[FF*DD];
__device__ __half g_w2h[DD*FF],     g_w2l[DD*FF];
__device__ __half g_p1h[HID*DD],    g_p1l[HID*DD];
__device__ __half g_p2h[HID*HID],   g_p2l[HID*HID];

// ---------------------------------------------------------------------------
// Helpers
// ---------------------------------------------------------------------------
__device__ __forceinline__ float gelu_f(float x) {
    return 0.5f * x * (1.0f + erff(x * 0.70710678118654752440f));
}

__device__ __forceinline__ void cp16(uint32_t dst, const void* src) {
    asm volatile("cp.async.cg.shared.global [%0], [%1], 16;\n"
                 :: "r"(dst), "l"(src));
}

__device__ __forceinline__ uint32_t smem_u32(const void* p) {
    uint32_t a;
    asm("{ .reg .u64 t; cvta.to.shared.u64 t, %1; cvt.u32.u64 %0, t; }"
        : "=r"(a) : "l"(p));
    return a;
}

// mma.sync m16n8k16 f16 with f32 accumulate
__device__ __forceinline__ void mma_f16(float* c,
                                        uint32_t a0, uint32_t a1,
                                        uint32_t a2, uint32_t a3,
                                        uint32_t b0, uint32_t b1) {
    asm volatile(
        "mma.sync.aligned.m16n8k16.row.col.f32.f16.f16.f32 "
        "{%0,%1,%2,%3}, {%4,%5,%6,%7}, {%8,%9}, {%0,%1,%2,%3};\n"
        : "+f"(c[0]), "+f"(c[1]), "+f"(c[2]), "+f"(c[3])
        : "r"(a0), "r"(a1), "r"(a2), "r"(a3), "r"(b0), "r"(b1));
}

__device__ __forceinline__ void ldsm_x4(uint32_t* r, uint32_t addr) {
    asm volatile(
        "ldmatrix.sync.aligned.m8n8.x4.shared.b16 {%0,%1,%2,%3}, [%4];\n"
        : "=r"(r[0]), "=r"(r[1]), "=r"(r[2]), "=r"(r[3]) : "r"(addr));
}

__device__ __forceinline__ void ldsm_x4_t(uint32_t* r, uint32_t addr) {
    asm volatile(
        "ldmatrix.sync.aligned.m8n8.x4.trans.shared.b16 {%0,%1,%2,%3}, [%4];\n"
        : "=r"(r[0]), "=r"(r[1]), "=r"(r[2]), "=r"(r[3]) : "r"(addr));
}

__device__ __forceinline__ void hsplit(float v, __half& h, __half& l) {
    h = __float2half(v);
    l = __float2half(v - __half2float(h));
}

// ---------------------------------------------------------------------------
// fp16 2-split GEMM, COMBOS = 3 (hh+hl+lh, fp32-grade) or 2 (hh+hl, ~2e-4).
// COMBOS==2: Al operand dropped entirely -> 3-array compact smem (60KB total).
// No min-blocks hint: register pressure must stay spill-free (R16 lesson).
// maxseg path: all-zero pooled row tile -> write const row, or return with no
// write when crf/crh are null (rows provably never read downstream).
// skipmask path: tile of dead (invalid-token) rows -> return, no write.
// ---------------------------------------------------------------------------
#define HS 40

template<int COMBOS>
__global__ __launch_bounds__(256)
void hgemm_kernel(const __half* __restrict__ Ah, const __half* __restrict__ Al,
                  const __half* __restrict__ Bh, const __half* __restrict__ Bl,
                  const float* __restrict__ bias, float* __restrict__ C,
                  __half* __restrict__ Ch, __half* __restrict__ Cl,
                  int M, int N, int K, int act, int out_split,
                  const float* __restrict__ maxseg,
                  const float* __restrict__ crf,
                  const __half* __restrict__ crh, const __half* __restrict__ crl,
                  const float* __restrict__ skipmask)
{
    extern __shared__ __half hsm[];
    constexpr uint32_t STG_H = (COMBOS == 3) ? 20480u : 15360u;  // halves/stage
    constexpr uint32_t ALO   = 5120u;                            // Al (3-combo)
    constexpr uint32_t BHO   = (COMBOS == 3) ? 10240u : 5120u;   // Bh offset

    const int tid  = threadIdx.x;
    const int wid  = tid >> 5;
    const int lane = tid & 31;
    const int gr   = lane >> 2;
    const int gc   = lane & 3;
    const int lg   = lane >> 3;
    const int lr   = lane & 7;

    // ---- grouped rasterization: groups of 16 M-tiles, rows vary fastest
    const int nbx = gridDim.x, nby = gridDim.y;
    int lin = blockIdx.y * nbx + blockIdx.x;
    const int GRP = 16;
    int grp  = lin / (GRP * nbx);
    int rem  = lin - grp * GRP * nbx;
    int rows = nby - grp * GRP; if (rows > GRP) rows = GRP;
    int by   = grp * GRP + rem % rows;
    int bx   = rem / rows;
    const int row0 = by * 128;
    const int col0 = bx * 128;

    // ---- dead-row tile skip (invalid tokens; prefix mask => whole tile dead)
    if (skipmask != nullptr) {
        if (skipmask[row0] <= 0.0f) return;
    }

    // ---- zero-row tile fast path (uniform branch)
    if (maxseg != nullptr) {
        int bb = row0 >> 10;
        int rloc = row0 & 1023;
        if ((float)rloc > maxseg[bb]) {
            if (!out_split) {
                if (crf == nullptr) return;   // rows never read downstream
                for (int idx = tid * 4; idx < 128 * 128; idx += 256 * 4) {
                    int r = idx >> 7, c = idx & 127;
                    *(float4*)(C + (size_t)(row0 + r) * N + col0 + c) =
                        *(const float4*)(crf + col0 + c);
                }
            } else {
                if (crh == nullptr) return;   // rows never read downstream
                for (int idx = tid * 8; idx < 128 * 128; idx += 256 * 8) {
                    int r = idx >> 7, c = idx & 127;
                    *(uint4*)(Ch + (size_t)(row0 + r) * N + col0 + c) =
                        *(const uint4*)(crh + col0 + c);
                    *(uint4*)(Cl + (size_t)(row0 + r) * N + col0 + c) =
                        *(const uint4*)(crl + col0 + c);
                }
            }
            return;
        }
    }

    const int warp_m = (wid & 3) * 32;
    const int warp_n = (wid >> 2) * 64;
    const uint32_t sbase = smem_u32(hsm);

    const int a_rowoff = (lg & 1) * 8 + lr;
    const int a_koff   = (lg >> 1) * 8;
    const int b_rowoff = (lg >> 1) * 8 + lr;
    const int b_koff   = (lg & 1) * 8;

    float acc[2][8][4];
#pragma unroll
    for (int i = 0; i < 2; i++)
#pragma unroll
        for (int j = 0; j < 8; j++)
#pragma unroll
            for (int r = 0; r < 4; r++) acc[i][j][r] = 0.0f;

    const int nk = K >> 5;
    const int c0i = tid * 2, c1i = tid * 2 + 1;
    const int m0 = c0i >> 2, kc0 = (c0i & 3) * 8;
    const int m1 = c1i >> 2, kc1 = (c1i & 3) * 8;

#define H_LOAD_STAGE(st, k0)                                                     \
    do {                                                                         \
        uint32_t b = sbase + (uint32_t)(st) * STG_H * 2u;                        \
        cp16(b + (uint32_t)(m0 * HS + kc0) * 2u,                                 \
             Ah + (size_t)(row0 + m0) * K + (k0) + kc0);                         \
        cp16(b + (uint32_t)(m1 * HS + kc1) * 2u,                                 \
             Ah + (size_t)(row0 + m1) * K + (k0) + kc1);                         \
        if (COMBOS == 3) {                                                       \
            cp16(b + (ALO + (uint32_t)(m0 * HS + kc0)) * 2u,                     \
                 Al + (size_t)(row0 + m0) * K + (k0) + kc0);                     \
            cp16(b + (ALO + (uint32_t)(m1 * HS + kc1)) * 2u,                     \
                 Al + (size_t)(row0 + m1) * K + (k0) + kc1);                     \
        }                                                                        \
        cp16(b + (BHO + (uint32_t)(m0 * HS + kc0)) * 2u,                         \
             Bh + (size_t)(col0 + m0) * K + (k0) + kc0);                         \
        cp16(b + (BHO + (uint32_t)(m1 * HS + kc1)) * 2u,                         \
             Bh + (size_t)(col0 + m1) * K + (k0) + kc1);                         \
        cp16(b + (BHO + 5120u + (uint32_t)(m0 * HS + kc0)) * 2u,                 \
             Bl + (size_t)(col0 + m0) * K + (k0) + kc0);                         \
        cp16(b + (BHO + 5120u + (uint32_t)(m1 * HS + kc1)) * 2u,                 \
             Bl + (size_t)(col0 + m1) * K + (k0) + kc1);                         \
        asm volatile("cp.async.commit_group;\n");                                \
    } while (0)

    H_LOAD_STAGE(0, 0);

    for (int t = 0; t < nk; t++) {
        const int st = t & 1;
        if (t + 1 < nk) {
            H_LOAD_STAGE((t + 1) & 1, (t + 1) << 5);
            asm volatile("cp.async.wait_group 1;\n");
        } else {
            asm volatile("cp.async.wait_group 0;\n");
        }
        __syncthreads();

        const uint32_t sg = sbase + (uint32_t)st * STG_H * 2u;

#pragma unroll
        for (int ks = 0; ks < 2; ks++) {
            const int kh = ks * 16;
            uint32_t ahf[2][4], alf[2][4];
#pragma unroll
            for (int mt = 0; mt < 2; mt++) {
                uint32_t aaddr = sg + (uint32_t)(
                    (warp_m + mt * 16 + a_rowoff) * HS + kh + a_koff) * 2u;
                ldsm_x4(ahf[mt], aaddr);
                if (COMBOS == 3)
                    ldsm_x4(alf[mt], aaddr + ALO * 2u);
            }
#pragma unroll
            for (int p = 0; p < 4; p++) {
                uint32_t baddr = sg + BHO * 2u + (uint32_t)(
                    (warp_n + p * 16 + b_rowoff) * HS + kh + b_koff) * 2u;
                uint32_t bhf[4], blf[4];
                ldsm_x4(bhf, baddr);
                ldsm_x4(blf, baddr + 5120u * 2u);
#pragma unroll
                for (int q = 0; q < 2; q++) {
                    const int nt = p * 2 + q;
                    uint32_t bh0 = bhf[q * 2], bh1 = bhf[q * 2 + 1];
                    uint32_t bl0 = blf[q * 2], bl1 = blf[q * 2 + 1];
#pragma unroll
                    for (int mt = 0; mt < 2; mt++) {
                        float* c = acc[mt][nt];
                        mma_f16(c, ahf[mt][0], ahf[mt][1], ahf[mt][2], ahf[mt][3], bh0, bh1);
                        mma_f16(c, ahf[mt][0], ahf[mt][1], ahf[mt][2], ahf[mt][3], bl0, bl1);
                        if (COMBOS == 3)
                            mma_f16(c, alf[mt][0], alf[mt][1], alf[mt][2], alf[mt][3], bh0, bh1);
                    }
                }
            }
        }
        __syncthreads();
    }

#pragma unroll
    for (int mt = 0; mt < 2; mt++) {
        const int r0 = row0 + warp_m + mt * 16 + gr;
#pragma unroll
        for (int nt = 0; nt < 8; nt++) {
            const int cc = col0 + warp_n + nt * 8 + 2 * gc;
            float b0v = bias[cc], b1v = bias[cc + 1];
            float v0 = acc[mt][nt][0] * WSCALE + b0v;
            float v1 = acc[mt][nt][1] * WSCALE + b1v;
            float v2 = acc[mt][nt][2] * WSCALE + b0v;
            float v3 = acc[mt][nt][3] * WSCALE + b1v;
            if (act == 1) {
                v0 = gelu_f(v0); v1 = gelu_f(v1);
                v2 = gelu_f(v2); v3 = gelu_f(v3);
            }
            if (!out_split) {
                *(float2*)(C + (size_t)r0 * N + cc)       = make_float2(v0, v1);
                *(float2*)(C + (size_t)(r0 + 8) * N + cc) = make_float2(v2, v3);
            } else {
                __half h0, l0, h1, l1;
                hsplit(v0, h0, l0); hsplit(v1, h1, l1);
                *(__half2*)(Ch + (size_t)r0 * N + cc) = __halves2half2(h0, h1);
                *(__half2*)(Cl + (size_t)r0 * N + cc) = __halves2half2(l0, l1);
                hsplit(v2, h0, l0); hsplit(v3, h1, l1);
                *(__half2*)(Ch + (size_t)(r0 + 8) * N + cc) = __halves2half2(h0, h1);
                *(__half2*)(Cl + (size_t)(r0 + 8) * N + cc) = __halves2half2(l0, l1);
            }
        }
    }
}

// ---------------------------------------------------------------------------
// Tensor-core flash attention (3-combo fp16, ldmatrix, trans-V).
// Q-tiles of invalid tokens (prefix mask) are dead -> early return.
// Mode 1: fully-masked key tiles skipped (contribution exactly 0).
// ---------------------------------------------------------------------------
#define HST 72
#define ATT_SMEM_BYTES (8 * 64 * HST * 2 + 64 * 4)

__global__ __launch_bounds__(128)
void attn_mma_kernel(const __half* __restrict__ qkvh, const __half* __restrict__ qkvl,
                     const float* __restrict__ masks,
                     int mode, __half* __restrict__ oh, __half* __restrict__ ol)
{
    extern __shared__ __half hs[];
    __half* Qh  = hs;
    __half* Ql  = Qh  + 64 * HST;
    __half* Kh  = Ql  + 64 * HST;
    __half* Kl  = Kh  + 64 * HST;
    __half* Vh  = Kl  + 64 * HST;
    __half* Vl  = Vh  + 64 * HST;
    __half* Psh = Vl  + 64 * HST;
    __half* Psl = Psh + 64 * HST;
    float*  mb  = (float*)(Psl + 64 * HST);

    const uint32_t sQh = smem_u32(Qh), sQl = smem_u32(Ql);
    const uint32_t sKh = smem_u32(Kh), sKl = smem_u32(Kl);
    const uint32_t sVh = smem_u32(Vh), sVl = smem_u32(Vl);
    const uint32_t sPh = smem_u32(Psh), sPl = smem_u32(Psl);

    const int tid  = threadIdx.x;
    const int wid  = tid >> 5;
    const int lane = tid & 31;
    const int gr   = lane >> 2;
    const int gc   = lane & 3;
    const int lg   = lane >> 3;
    const int lr   = lane & 7;
    const int q0   = blockIdx.x * 64;
    const int b    = blockIdx.y >> 4;
    const int h    = blockIdx.y & 15;
    const size_t qbase = (size_t)b * SS * QKVN + (size_t)h * HDIM;
    const size_t obase = (size_t)b * SS * DD + (size_t)h * HDIM;
    const int q0w = wid * 16;

    // dead q-tile skip: invalid queries never influence the final output
    if (masks[b * SS + q0] <= 0.0f) return;

    const int a_ro = (lg & 1) * 8 + lr;
    const int a_ko = (lg >> 1) * 8;
    const int b_ro = (lg >> 1) * 8 + lr;
    const int b_ko = (lg & 1) * 8;
    const int v_ko = (lg & 1) * 8 + lr;
    const int v_do = (lg >> 1) * 8;

    for (int idx = tid; idx < 512; idx += 128) {
        int r = idx >> 3, c8 = (idx & 7) << 3;
        uint32_t soff = (uint32_t)(r * HST + c8) * 2u;
        cp16(sQh + soff, qkvh + qbase + (size_t)(q0 + r) * QKVN + c8);
        cp16(sQl + soff, qkvl + qbase + (size_t)(q0 + r) * QKVN + c8);
    }
    asm volatile("cp.async.commit_group;\n");

    float mrow[2] = {-1e30f, -1e30f};
    float lrow[2] = {0.0f, 0.0f};
    float Oacc[8][4];
#pragma unroll
    for (int i = 0; i < 8; i++)
#pragma unroll
        for (int j = 0; j < 4; j++) Oacc[i][j] = 0.0f;

    for (int t = 0; t < 16; t++) {
        const int k0 = t * 64;
        if (mode == 1 && masks[b * SS + k0] <= 0.0f) continue;

        for (int idx = tid; idx < 512; idx += 128) {
            int r = idx >> 3, c8 = (idx & 7) << 3;
            uint32_t soff = (uint32_t)(r * HST + c8) * 2u;
            size_t kg = qbase + 1024 + (size_t)(k0 + r) * QKVN + c8;
            size_t vg = qbase + 2048 + (size_t)(k0 + r) * QKVN + c8;
            cp16(sKh + soff, qkvh + kg);
            cp16(sKl + soff, qkvl + kg);
            cp16(sVh + soff, qkvh + vg);
            cp16(sVl + soff, qkvl + vg);
        }
        asm volatile("cp.async.commit_group;\n");
        if (tid < 64) {
            float mv = masks[b * SS + k0 + tid];
            mb[tid] = (mode == 0) ? mv : (mv > 0.0f ? 0.0f : -1e9f);
        }
        asm volatile("cp.async.wait_group 0;\n");
        __syncthreads();

        float S[8][4];
#pragma unroll
        for (int i = 0; i < 8; i++)
#pragma unroll
            for (int j = 0; j < 4; j++) S[i][j] = 0.0f;

#pragma unroll
        for (int kh = 0; kh < 64; kh += 16) {
            uint32_t qhf[4], qlf[4];
            {
                uint32_t qaddr = (uint32_t)((q0w + a_ro) * HST + kh + a_ko) * 2u;
                ldsm_x4(qhf, sQh + qaddr);
                ldsm_x4(qlf, sQl + qaddr);
            }
#pragma unroll
            for (int p = 0; p < 4; p++) {
                uint32_t kaddr = (uint32_t)((p * 16 + b_ro) * HST + kh + b_ko) * 2u;
                uint32_t khf[4], klf[4];
                ldsm_x4(khf, sKh + kaddr);
                ldsm_x4(klf, sKl + kaddr);
#pragma unroll
                for (int q = 0; q < 2; q++) {
                    const int nt = p * 2 + q;
                    uint32_t kh0 = khf[q * 2], kh1 = khf[q * 2 + 1];
                    uint32_t kl0 = klf[q * 2], kl1 = klf[q * 2 + 1];
                    mma_f16(S[nt], qhf[0], qhf[1], qhf[2], qhf[3], kh0, kh1);
                    mma_f16(S[nt], qhf[0], qhf[1], qhf[2], qhf[3], kl0, kl1);
                    mma_f16(S[nt], qlf[0], qlf[1], qlf[2], qlf[3], kh0, kh1);
                }
            }
        }

        float rmax[2] = {-1e30f, -1e30f};
#pragma unroll
        for (int nt = 0; nt < 8; nt++) {
            float m0 = mb[nt * 8 + 2 * gc];
            float m1 = mb[nt * 8 + 2 * gc + 1];
            S[nt][0] = S[nt][0] * 0.125f + m0;
            S[nt][1] = S[nt][1] * 0.125f + m1;
            S[nt][2] = S[nt][2] * 0.125f + m0;
            S[nt][3] = S[nt][3] * 0.125f + m1;
            rmax[0] = fmaxf(rmax[0], fmaxf(S[nt][0], S[nt][1]));
            rmax[1] = fmaxf(rmax[1], fmaxf(S[nt][2], S[nt][3]));
        }
#pragma unroll
        for (int sh = 1; sh < 4; sh <<= 1) {
            rmax[0] = fmaxf(rmax[0], __shfl_xor_sync(0xffffffffu, rmax[0], sh));
            rmax[1] = fmaxf(rmax[1], __shfl_xor_sync(0xffffffffu, rmax[1], sh));
        }
        float mnew0 = fmaxf(mrow[0], rmax[0]);
        float mnew1 = fmaxf(mrow[1], rmax[1]);
        float scl0 = __expf(mrow[0] - mnew0);
        float scl1 = __expf(mrow[1] - mnew1);
        float rsum[2] = {0.0f, 0.0f};
#pragma unroll
        for (int nt = 0; nt < 8; nt++) {
            S[nt][0] = __expf(S[nt][0] - mnew0);
            S[nt][1] = __expf(S[nt][1] - mnew0);
            S[nt][2] = __expf(S[nt][2] - mnew1);
            S[nt][3] = __expf(S[nt][3] - mnew1);
            rsum[0] += S[nt][0] + S[nt][1];
            rsum[1] += S[nt][2] + S[nt][3];
        }
#pragma unroll
        for (int sh = 1; sh < 4; sh <<= 1) {
            rsum[0] += __shfl_xor_sync(0xffffffffu, rsum[0], sh);
            rsum[1] += __shfl_xor_sync(0xffffffffu, rsum[1], sh);
        }
        lrow[0] = lrow[0] * scl0 + rsum[0];
        lrow[1] = lrow[1] * scl1 + rsum[1];
        mrow[0] = mnew0; mrow[1] = mnew1;
#pragma unroll
        for (int dt = 0; dt < 8; dt++) {
            Oacc[dt][0] *= scl0; Oacc[dt][1] *= scl0;
            Oacc[dt][2] *= scl1; Oacc[dt][3] *= scl1;
        }

        __syncwarp();
#pragma unroll
        for (int nt = 0; nt < 8; nt++) {
            int c0 = nt * 8 + 2 * gc;
            __half h0, l0, h1, l1;
            hsplit(S[nt][0], h0, l0); hsplit(S[nt][1], h1, l1);
            *(__half2*)(Psh + (q0w + gr) * HST + c0) = __halves2half2(h0, h1);
            *(__half2*)(Psl + (q0w + gr) * HST + c0) = __halves2half2(l0, l1);
            hsplit(S[nt][2], h0, l0); hsplit(S[nt][3], h1, l1);
            *(__half2*)(Psh + (q0w + gr + 8) * HST + c0) = __halves2half2(h0, h1);
            *(__half2*)(Psl + (q0w + gr + 8) * HST + c0) = __halves2half2(l0, l1);
        }
        __syncwarp();

#pragma unroll
        for (int kh = 0; kh < 64; kh += 16) {
            uint32_t phf[4], plf[4];
            {
                uint32_t paddr = (uint32_t)((q0w + a_ro) * HST + kh + a_ko) * 2u;
                ldsm_x4(phf, sPh + paddr);
                ldsm_x4(plf, sPl + paddr);
            }
#pragma unroll
            for (int p = 0; p < 4; p++) {
                const int d0 = p * 16;
                uint32_t vaddr = (uint32_t)((kh + v_ko) * HST + d0 + v_do) * 2u;
                uint32_t vhf[4], vlf[4];
                ldsm_x4_t(vhf, sVh + vaddr);
                ldsm_x4_t(vlf, sVl + vaddr);
#pragma unroll
                for (int q = 0; q < 2; q++) {
                    const int dt = p * 2 + q;
                    uint32_t vh0 = vhf[q * 2], vh1 = vhf[q * 2 + 1];
                    uint32_t vl0 = vlf[q * 2], vl1 = vlf[q * 2 + 1];
                    mma_f16(Oacc[dt], phf[0], phf[1], phf[2], phf[3], vh0, vh1);
                    mma_f16(Oacc[dt], phf[0], phf[1], phf[2], phf[3], vl0, vl1);
                    mma_f16(Oacc[dt], plf[0], plf[1], plf[2], plf[3], vh0, vh1);
                }
            }
        }
        __syncthreads();
    }

    float inv0 = 1.0f / lrow[0];
    float inv1 = 1.0f / lrow[1];
    const int r0 = q0 + q0w + gr;
#pragma unroll
    for (int dt = 0; dt < 8; dt++) {
        int col = dt * 8 + 2 * gc;
        __half h0, l0, h1, l1;
        hsplit(Oacc[dt][0] * inv0, h0, l0);
        hsplit(Oacc[dt][1] * inv0, h1, l1);
        *(__half2*)(oh + obase + (size_t)r0 * DD + col) = __halves2half2(h0, h1);
        *(__half2*)(ol + obase + (size_t)r0 * DD + col) = __halves2half2(l0, l1);
        hsplit(Oacc[dt][2] * inv1, h0, l0);
        hsplit(Oacc[dt][3] * inv1, h1, l1);
        *(__half2*)(oh + obase + (size_t)(r0 + 8) * DD + col) = __halves2half2(h0, h1);
        *(__half2*)(ol + obase + (size_t)(r0 + 8) * DD + col) = __halves2half2(l0, l1);
    }
}

// ---------------------------------------------------------------------------
// Transpose + scale x64 + fp16 split, 64x64 tiles, vectorized.
// ---------------------------------------------------------------------------
__device__ __forceinline__ void trans_split_tile(
    const float* W, __half* Wh, __half* Wl, int Kd, int Nd,
    int n0, int k0, float (*t)[65])
{
    const int tx = threadIdx.x & 15;
    const int ty = threadIdx.x >> 4;

#pragma unroll
    for (int r = ty; r < 64; r += 16) {
        float4 v = *(const float4*)(W + (size_t)(k0 + r) * Nd + n0 + tx * 4);
        t[r][tx * 4 + 0] = v.x;
        t[r][tx * 4 + 1] = v.y;
        t[r][tx * 4 + 2] = v.z;
        t[r][tx * 4 + 3] = v.w;
    }
    __syncthreads();

#pragma unroll
    for (int n = ty; n < 64; n += 16) {
        float a0 = t[tx * 4 + 0][n] * 64.0f;
        float a1 = t[tx * 4 + 1][n] * 64.0f;
        float a2 = t[tx * 4 + 2][n] * 64.0f;
        float a3 = t[tx * 4 + 3][n] * 64.0f;
        __half hv[4], lv[4];
        hsplit(a0, hv[0], lv[0]); hsplit(a1, hv[1], lv[1]);
        hsplit(a2, hv[2], lv[2]); hsplit(a3, hv[3], lv[3]);
        *(uint2*)(Wh + (size_t)(n0 + n) * Kd + k0 + tx * 4) = *(uint2*)hv;
        *(uint2*)(Wl + (size_t)(n0 + n) * Kd + k0 + tx * 4) = *(uint2*)lv;
    }
}

__global__ __launch_bounds__(256)
void trans_split_h_kernel(const float* __restrict__ W,
                          __half* __restrict__ Wh, __half* __restrict__ Wl,
                          int Kd, int Nd)
{
    __shared__ float t[64][65];
    trans_split_tile(W, Wh, Wl, Kd, Nd, blockIdx.x * 64, blockIdx.y * 64, t);
}

// merged variant: 4 same-shape 1024x1024 weights, z selects source
__global__ __launch_bounds__(256)
void trans_split4_kernel(const float* __restrict__ W0, const float* __restrict__ W1,
                         const float* __restrict__ W2, const float* __restrict__ W3,
                         __half* __restrict__ H0, __half* __restrict__ L0,
                         __half* __restrict__ H1, __half* __restrict__ L1,
                         __half* __restrict__ H2, __half* __restrict__ L2,
                         __half* __restrict__ H3, __half* __restrict__ L3)
{
    __shared__ float t[64][65];
    const float* W; __half* Wh; __half* Wl;
    switch (blockIdx.z) {
        case 0: W = W0; Wh = H0; Wl = L0; break;
        case 1: W = W1; Wh = H1; Wl = L1; break;
        case 2: W = W2; Wh = H2; Wl = L2; break;
        default: W = W3; Wh = H3; Wl = L3; break;
    }
    trans_split_tile(W, Wh, Wl, DD, DD, blockIdx.x * 64, blockIdx.y * 64, t);
}

// ---------------------------------------------------------------------------
// Elementwise fp16 split, vectorized x4
// ---------------------------------------------------------------------------
__global__ __launch_bounds__(256)
void split_h_kernel(const float* __restrict__ a, __half* __restrict__ ah,
                    __half* __restrict__ al, int n)
{
    int i = (blockIdx.x * 256 + threadIdx.x) * 4;
    if (i < n) {
        float4 v = *(const float4*)(a + i);
        __half hv[4], lv[4];
        hsplit(v.x, hv[0], lv[0]); hsplit(v.y, hv[1], lv[1]);
        hsplit(v.z, hv[2], lv[2]); hsplit(v.w, hv[3], lv[3]);
        *(uint2*)(ah + i) = *(uint2*)hv;
        *(uint2*)(al + i) = *(uint2*)lv;
    }
}

__global__ __launch_bounds__(256)
void concat_bias_kernel(const float* __restrict__ bq, const float* __restrict__ bk,
                        const float* __restrict__ bv, float* __restrict__ bqkv)
{
    int i = blockIdx.x * 256 + threadIdx.x;
    if (i < QKVN) {
        float v = (i < 1024) ? bq[i] : ((i < 2048) ? bk[i - 1024] : bv[i - 2048]);
        bqkv[i] = v;
    }
}

// const row 1: c1 = gelu(bp1)
__global__ __launch_bounds__(256)
void const_row1_kernel(const float* __restrict__ bp1, float* __restrict__ c1f,
                       __half* __restrict__ c1h, __half* __restrict__ c1l)
{
    int i = blockIdx.x * 256 + threadIdx.x;
    if (i < HID) {
        float v = gelu_f(bp1[i]);
        c1f[i] = v;
        __half h, l;
        hsplit(v, h, l);
        c1h[i] = h; c1l[i] = l;
    }
}

// const row 2: c2 = c1 @ P2 + bp2 (fp32 GEMV over split-transposed P2)
__global__ __launch_bounds__(256)
void const_row2_kernel(const float* __restrict__ c1f,
                       const __half* __restrict__ p2h, const __half* __restrict__ p2l,
                       const float* __restrict__ bp2, float* __restrict__ c2f)
{
    int n = blockIdx.x * 8 + (threadIdx.x >> 5);
    int lane = threadIdx.x & 31;
    const __half* rh = p2h + (size_t)n * HID;
    const __half* rl = p2l + (size_t)n * HID;
    float acc = 0.0f;
    for (int k = lane; k < HID; k += 32)
        acc += c1f[k] * (__half2float(rh[k]) + __half2float(rl[k]));
#pragma unroll
    for (int m = 16; m; m >>= 1) acc += __shfl_xor_sync(0xffffffffu, acc, m);
    if (lane == 0) c2f[n] = acc * WSCALE + bp2[n];
}

// ---------------------------------------------------------------------------
// out = LayerNorm(a + b) * g + beta ; fp16 split out; dead rows skipped
// ---------------------------------------------------------------------------
__global__ __launch_bounds__(256)
void add_ln_kernel(const float* __restrict__ a, const float* __restrict__ b2,
                   const float* __restrict__ g, const float* __restrict__ beta,
                   float* __restrict__ out,
                   __half* __restrict__ outh, __half* __restrict__ outl,
                   const float* __restrict__ vmask)
{
    const int row = blockIdx.x;
    if (vmask[row] <= 0.0f) return;
    const size_t off = (size_t)row * DD;
    const int t = threadIdx.x;
    __shared__ float r1[256], r2[256];

    float vloc[4];
    float s = 0.0f, s2 = 0.0f;
#pragma unroll
    for (int i = 0; i < 4; i++) {
        int d = t + i * 256;
        float vv = a[off + d] + b2[off + d];
        vloc[i] = vv;
        s += vv; s2 += vv * vv;
    }
    r1[t] = s; r2[t] = s2;
    __syncthreads();
    for (int o2 = 128; o2 > 0; o2 >>= 1) {
        if (t < o2) { r1[t] += r1[t + o2]; r2[t] += r2[t + o2]; }
        __syncthreads();
    }
    float mean = r1[0] * (1.0f / DD);
    float var  = r2[0] * (1.0f / DD) - mean * mean;
    float inv  = rsqrtf(var + 1e-5f);
#pragma unroll
    for (int i = 0; i < 4; i++) {
        int d = t + i * 256;
        float vv = (vloc[i] - mean) * inv * g[d] + beta[d];
        out[off + d] = vv;
        __half h, l;
        hsplit(vv, h, l);
        outh[off + d] = h;
        outl[off + d] = l;
    }
}

__global__ __launch_bounds__(256)
void score_kernel(const float* __restrict__ feat, const float* __restrict__ Ws,
                  const float* __restrict__ bs, float* __restrict__ sbuf)
{
    int token = blockIdx.x * 8 + (threadIdx.x >> 5);
    int lane  = threadIdx.x & 31;
    const float* f = feat + (size_t)token * DD;
    float acc = 0.0f;
    for (int i = lane; i < DD; i += 32) acc += f[i] * Ws[i];
#pragma unroll
    for (int m = 16; m; m >>= 1) acc += __shfl_xor_sync(0xffffffffu, acc, m);
    if (lane == 0) sbuf[token] = 1.0f / (1.0f + expf(-(acc + bs[0])));
}

__global__ __launch_bounds__(1024)
void scan_kernel(const float* __restrict__ sbuf, const float* __restrict__ masks,
                 float* __restrict__ svbuf, int* __restrict__ segbuf,
                 float* __restrict__ maxseg)
{
    const int b = blockIdx.x;
    const int t = threadIdx.x;
    __shared__ float sc[SS];
    __shared__ float mr[SS];

    float valid = masks[b * SS + t];
    float sv = (valid > 0.0f) ? sbuf[b * SS + t] : 0.0f;
    svbuf[b * SS + t] = sv;
    sc[t] = sv;
    __syncthreads();
    for (int off = 1; off < SS; off <<= 1) {
        float vprev = (t >= off) ? sc[t - off] : 0.0f;
        __syncthreads();
        sc[t] += vprev;
        __syncthreads();
    }
    float c = floorf(sc[t]);
    int seg = (int)c;
    seg = seg < 0 ? 0 : (seg > SS - 1 ? SS - 1 : seg);
    segbuf[b * SS + t] = seg;

    mr[t] = (valid > 0.0f) ? c : -1.0f;
    __syncthreads();
    for (int off = 512; off > 0; off >>= 1) {
        if (t < off) mr[t] = fmaxf(mr[t], mr[t + off]);
        __syncthreads();
    }
    if (t == 0) maxseg[b] = mr[0];
}

// ---------------------------------------------------------------------------
// pooled[b,g,:] = segment-sum; blocks in fully-skipped P1 tiles are dead
// ---------------------------------------------------------------------------
__global__ __launch_bounds__(256)
void pool_kernel(const float* __restrict__ x, const float* __restrict__ svbuf,
                 const int* __restrict__ segbuf,
                 __half* __restrict__ ph, __half* __restrict__ pl,
                 const float* __restrict__ maxseg)
{
    const int g = blockIdx.x;
    const int b = blockIdx.y;
    if ((float)(g & ~127) > maxseg[b]) return;

    const int* seg = segbuf + b * SS;

    int lo = 0, hi = SS;
    while (lo < hi) { int mid = (lo + hi) >> 1; if (seg[mid] < g) lo = mid + 1; else hi = mid; }
    int beg = lo;
    lo = beg; hi = SS;
    while (lo < hi) { int mid = (lo + hi) >> 1; if (seg[mid] < g + 1) lo = mid + 1; else hi = mid; }
    int end = lo;

    const int t = threadIdx.x;
    float acc[4] = {0.0f, 0.0f, 0.0f, 0.0f};
    for (int s = beg; s < end; s++) {
        float w = svbuf[b * SS + s];
        const float* xr = x + ((size_t)b * SS + s) * DD;
#pragma unroll
        for (int i = 0; i < 4; i++) acc[i] += xr[t + i * 256] * w;
    }
    size_t rbase = ((size_t)b * SS + g) * DD;
#pragma unroll
    for (int i = 0; i < 4; i++) {
        __half h, l;
        hsplit(acc[i], h, l);
        ph[rbase + t + i * 256] = h;
        pl[rbase + t + i * 256] = l;
    }
}

__global__ __launch_bounds__(1024)
void mask_kernel(const float* __restrict__ maxseg, float* __restrict__ outmask)
{
    const int b = blockIdx.x;
    const int t = threadIdx.x;
    outmask[b * SS + t] = ((float)t <= maxseg[b]) ? 1.0f : 0.0f;
}

// ---------------------------------------------------------------------------
// Host side
// ---------------------------------------------------------------------------
static void* sym_addr(const void* sym) {
    void* p = nullptr;
    cudaGetSymbolAddress(&p, sym);
    return p;
}

#define H_SMEM3 (2 * 20480 * 2)
#define H_SMEM2 (2 * 15360 * 2)

static void launch_hgemm(const __half* Ah, const __half* Al,
                         const __half* Bh, const __half* Bl,
                         const float* bias, float* C,
                         __half* Ch, __half* Cl,
                         int M, int N, int K, int act, int out_split,
                         int combos,
                         const float* maxseg = nullptr,
                         const float* crf = nullptr,
                         const __half* crh = nullptr,
                         const __half* crl = nullptr,
                         const float* skipmask = nullptr) {
    dim3 grid(N / 128, M / 128);
    if (combos == 3)
        hgemm_kernel<3><<<grid, 256, H_SMEM3>>>(Ah, Al, Bh, Bl, bias, C,
                                                Ch, Cl, M, N, K, act, out_split,
                                                maxseg, crf, crh, crl, skipmask);
    else
        hgemm_kernel<2><<<grid, 256, H_SMEM2>>>(Ah, Al, Bh, Bl, bias, C,
                                                Ch, Cl, M, N, K, act, out_split,
                                                maxseg, crf, crh, crl, skipmask);
}

extern "C" void kernel_launch(void* const* d_in, const int* in_sizes, int n_in,
                              void* d_out, int out_size)
{
    (void)in_sizes; (void)n_in;
    const float* x     = (const float*)d_in[0];
    const float* masks = (const float*)d_in[1];
    const float* Wq  = (const float*)d_in[2];
    const float* bq  = (const float*)d_in[3];
    const float* Wk  = (const float*)d_in[4];
    const float* bk  = (const float*)d_in[5];
    const float* Wv  = (const float*)d_in[6];
    const float* bv  = (const float*)d_in[7];
    const float* Wo  = (const float*)d_in[8];
    const float* bo  = (const float*)d_in[9];
    const float* g1  = (const float*)d_in[10];
    const float* be1 = (const float*)d_in[11];
    const float* g2  = (const float*)d_in[12];
    const float* be2 = (const float*)d_in[13];
    const float* W1  = (const float*)d_in[14];
    const float* bf1 = (const float*)d_in[15];
    const float* W2  = (const float*)d_in[16];
    const float* bf2 = (const float*)d_in[17];
    const float* Ws  = (const float*)d_in[18];
    const float* bs  = (const float*)d_in[19];
    const float* P1  = (const float*)d_in[20];
    const float* bp1 = (const float*)d_in[21];
    const float* P2  = (const float*)d_in[22];
    const float* bp2 = (const float*)d_in[23];

    float* out = (float*)d_out;
    (void)out_size;

    cudaFuncSetAttribute(attn_mma_kernel,
                         cudaFuncAttributeMaxDynamicSharedMemorySize,
                         ATT_SMEM_BYTES);
    cudaFuncSetAttribute(hgemm_kernel<3>,
                         cudaFuncAttributeMaxDynamicSharedMemorySize, H_SMEM3);
    cudaFuncSetAttribute(hgemm_kernel<2>,
                         cudaFuncAttributeMaxDynamicSharedMemorySize, H_SMEM2);

    float* ob    = (float*)sym_addr(g_o);
    float* hb    = (float*)sym_addr(g_h);
    float* featb = (float*)sym_addr(g_feat);
    float* feat2b= (float*)sym_addr(g_feat2);
    float* sb    = (float*)sym_addr(g_s);
    float* svb   = (float*)sym_addr(g_sv);
    int*   segb  = (int*)sym_addr(g_seg);
    float* msb   = (float*)sym_addr(g_maxseg);
    float* bqkvb = (float*)sym_addr(g_bqkv);
    float* c1f   = (float*)sym_addr(g_c1f);
    float* c2f   = (float*)sym_addr(g_c2f);

    __half* c1h = (__half*)sym_addr(g_c1h);
    __half* c1l = (__half*)sym_addr(g_c1l);
    __half* qkvh = (__half*)sym_addr(g_qkvh);
    __half* qkvl = (__half*)sym_addr(g_qkvl);
    __half* xh  = (__half*)sym_addr(g_xh);
    __half* xl  = (__half*)sym_addr(g_xl);
    __half* fh  = (__half*)sym_addr(g_fh);
    __half* fl  = (__half*)sym_addr(g_fl);
    __half* ath = (__half*)sym_addr(g_ath);
    __half* atl = (__half*)sym_addr(g_atl);
    __half* hh  = (__half*)sym_addr(g_hh);
    __half* hl  = (__half*)sym_addr(g_hl);
    __half* ffh = (__half*)sym_addr(g_ffh);
    __half* ffl = (__half*)sym_addr(g_ffl);
    __half* plh = (__half*)sym_addr(g_plh);
    __half* pll = (__half*)sym_addr(g_pll);
    __half* phh = (__half*)sym_addr(g_phh);
    __half* phl = (__half*)sym_addr(g_phl);

    __half* wqkvh = (__half*)sym_addr(g_wqkvh);
    __half* wqkvl = (__half*)sym_addr(g_wqkvl);
    __half* woh = (__half*)sym_addr(g_woh);
    __half* wol = (__half*)sym_addr(g_wol);
    __half* w1h = (__half*)sym_addr(g_w1h);
    __half* w1l = (__half*)sym_addr(g_w1l);
    __half* w2h = (__half*)sym_addr(g_w2h);
    __half* w2l = (__half*)sym_addr(g_w2l);
    __half* p1h = (__half*)sym_addr(g_p1h);
    __half* p1l = (__half*)sym_addr(g_p1l);
    __half* p2h = (__half*)sym_addr(g_p2h);
    __half* p2l = (__half*)sym_addr(g_p2l);

    // ---- weight prep: merged 4x 1024^2 transpose-split + the rest ----
    trans_split4_kernel<<<dim3(DD / 64, DD / 64, 4), 256>>>(
        Wq, Wk, Wv, Wo,
        wqkvh, wqkvl,
        wqkvh + DD * DD, wqkvl + DD * DD,
        wqkvh + 2 * DD * DD, wqkvl + 2 * DD * DD,
        woh, wol);
    trans_split_h_kernel<<<dim3(FF / 64, DD / 64), 256>>>(W1, w1h, w1l, DD, FF);
    trans_split_h_kernel<<<dim3(DD / 64, FF / 64), 256>>>(W2, w2h, w2l, FF, DD);
    trans_split_h_kernel<<<dim3(HID / 64, DD / 64), 256>>>(P1, p1h, p1l, DD, HID);
    trans_split_h_kernel<<<dim3(HID / 64, HID / 64), 256>>>(P2, p2h, p2l, HID, HID);
    concat_bias_kernel<<<(QKVN + 255) / 256, 256>>>(bq, bk, bv, bqkvb);
    split_h_kernel<<<(TOK * DD / 4 + 255) / 256, 256>>>(x, xh, xl, TOK * DD);
    const_row1_kernel<<<(HID + 255) / 256, 256>>>(bp1, c1f, c1h, c1l);
    const_row2_kernel<<<HID / 8, 256>>>(c1f, p2h, p2l, bp2, c2f);

    // ---- encoder layer, applied twice (3 combos: exact path) ----
    const __half* inh = xh;
    const __half* inl = xl;
    const float* enc_in = x;
    float* enc_out = featb;
    for (int pass = 0; pass < 2; pass++) {
        int mode = pass;
        const float* qkv_skip = (pass == 0) ? nullptr : masks;
        launch_hgemm(inh, inl, wqkvh, wqkvl, bqkvb, nullptr, qkvh, qkvl,
                     TOK, QKVN, DD, 0, 1, 3,
                     nullptr, nullptr, nullptr, nullptr, qkv_skip);
        attn_mma_kernel<<<dim3(SS / 64, BB * HH), 128, ATT_SMEM_BYTES>>>(
            qkvh, qkvl, masks, mode, ath, atl);
        launch_hgemm(ath, atl, woh, wol, bo, ob, nullptr, nullptr,
                     TOK, DD, DD, 0, 0, 3,
                     nullptr, nullptr, nullptr, nullptr, masks);
        add_ln_kernel<<<TOK, 256>>>(enc_in, ob, g1, be1, hb, hh, hl, masks);
        launch_hgemm(hh, hl, w1h, w1l, bf1, nullptr, ffh, ffl,
                     TOK, FF, DD, 1, 1, 3,
                     nullptr, nullptr, nullptr, nullptr, masks);
        launch_hgemm(ffh, ffl, w2h, w2l, bf2, ob, nullptr, nullptr,
                     TOK, DD, FF, 0, 0, 3,
                     nullptr, nullptr, nullptr, nullptr, masks);
        add_ln_kernel<<<TOK, 256>>>(hb, ob, g2, be2, enc_out, fh, fl, masks);
        enc_in = featb;
        enc_out = feat2b;
        inh = fh; inl = fl;
    }

    // ---- importance scores, cumsum segmentation ----
    score_kernel<<<TOK / 8, 256>>>(feat2b, Ws, bs, sb);
    scan_kernel<<<BB, 1024>>>(sb, masks, svb, segb, msb);

    // ---- weighted segment-sum pooling of original x (split fp16 output) ----
    pool_kernel<<<dim3(SS, BB), 256>>>(x, svb, segb, plh, pll, msb);

    // ---- projector: 2-combo compact-smem fp16 + zero-row tile skip ----
    launch_hgemm(plh, pll, p1h, p1l, bp1, nullptr, phh, phl,
                 TOK, HID, DD, 1, 1, 2, msb, nullptr, nullptr, nullptr);
    launch_hgemm(phh, phl, p2h, p2l, bp2, out, nullptr, nullptr,
                 TOK, HID, HID, 0, 0, 2, msb, c2f, nullptr, nullptr);

    // ---- new_mask appended after the [B,S,HID] output ----
    mask_kernel<<<BB, 1024>>>(msb, out + (size_t)TOK * HID);
}